// round 16
// baseline (speedup 1.0000x reference)
#include <cuda_runtime.h>
#include <cuda_fp16.h>
#include <math.h>
#include <stdint.h>

// Problem constants
#define BB 2
#define SS 2048
#define DD 2048
#define HH 16
#define NOPE 128
#define ROPE_D 64
#define VD 128
#define KV_RANK 512
#define Q_RANK 1536
#define QH (NOPE + ROPE_D)   // 192
#define KVH (NOPE + VD)      // 256
#define RTOT (BB * SS)       // 4096 rows
#define N1 (Q_RANK + KV_RANK + ROPE_D)   // 2112

// ---------------- scratch (device globals, no allocation) ----------------
__device__ float g_c1 [RTOT * N1];
__device__ float g_cos[SS * (ROPE_D / 2)];
__device__ float g_sin[SS * (ROPE_D / 2)];
__device__ __half g_xh  [RTOT * DD];
__device__ __half g_w1T [N1 * DD];
__device__ __half g_wuqT [HH * QH * Q_RANK];
__device__ __half g_wukvT[HH * KVH * KV_RANK];
__device__ __half g_woT  [DD * HH * VD];
__device__ __half g_cqh [RTOT * Q_RANK];
__device__ __half g_kvah[RTOT * KV_RANK];
__device__ __half g_oh  [RTOT * (HH * VD)];
__device__ __half g_qh  [RTOT * (HH * QH)];
__device__ __half g_kvh [RTOT * (HH * KVH)];
__device__ __half g_kpeh[RTOT * ROPE_D];

// ---------------- helpers -------------------------------------------------
__device__ __forceinline__ unsigned h2u(float a, float b) {
    __half2 h = __floats2half2_rn(a, b);
    return *(unsigned*)&h;
}

__device__ __forceinline__ void mma_f16(float c[4], const unsigned a[4], const unsigned b[2]) {
    asm volatile(
        "mma.sync.aligned.m16n8k16.row.col.f32.f16.f16.f32 "
        "{%0,%1,%2,%3}, {%4,%5,%6,%7}, {%8,%9}, {%0,%1,%2,%3};\n"
        : "+f"(c[0]), "+f"(c[1]), "+f"(c[2]), "+f"(c[3])
        : "r"(a[0]), "r"(a[1]), "r"(a[2]), "r"(a[3]), "r"(b[0]), "r"(b[1]));
}

__device__ __forceinline__ void ldmx4(unsigned& d0, unsigned& d1, unsigned& d2,
                                      unsigned& d3, uint32_t a) {
    asm volatile("ldmatrix.sync.aligned.m8n8.x4.shared.b16 {%0,%1,%2,%3}, [%4];"
                 : "=r"(d0), "=r"(d1), "=r"(d2), "=r"(d3) : "r"(a));
}
__device__ __forceinline__ void ldmx4t(unsigned& d0, unsigned& d1, unsigned& d2,
                                       unsigned& d3, uint32_t a) {
    asm volatile("ldmatrix.sync.aligned.m8n8.x4.trans.shared.b16 {%0,%1,%2,%3}, [%4];"
                 : "=r"(d0), "=r"(d1), "=r"(d2), "=r"(d3) : "r"(a));
}

__device__ __forceinline__ void cpa16(uint32_t dst_smem, const void* src) {
    asm volatile("cp.async.cg.shared.global [%0], [%1], 16;\n" :: "r"(dst_smem), "l"(src));
}
#define CP_COMMIT() asm volatile("cp.async.commit_group;\n")
#define CP_WAIT(n)  asm volatile("cp.async.wait_group %0;\n" :: "n"(n))

__device__ __forceinline__ uint32_t smem_u32(const void* p) {
    uint32_t a;
    asm("{ .reg .u64 t; cvta.to.shared.u64 t, %1; cvt.u32.u64 %0, t; }" : "=r"(a) : "l"(p));
    return a;
}

// ---------------- fp32 -> fp16 linear convert -----------------------------
__global__ void cvth_k(const float4* __restrict__ in, __half* __restrict__ out, int n4)
{
    int i = blockIdx.x * blockDim.x + threadIdx.x;
    int stride = gridDim.x * blockDim.x;
    for (; i < n4; i += stride) {
        float4 v = in[i];
        uint2 w;
        w.x = h2u(v.x, v.y);
        w.y = h2u(v.z, v.w);
        *(uint2*)(out + (size_t)i * 4) = w;
    }
}

// ---------------- transpose + fp16: in[R][C] fp32 -> out[C][R] half -------
__global__ __launch_bounds__(256) void trth_k(const float* __restrict__ in,
                                              __half* __restrict__ out, int R, int C)
{
    __shared__ float tl[32][33];
    int c0 = blockIdx.x * 32, r0 = blockIdx.y * 32;
    int tx = threadIdx.x & 31, ty = threadIdx.x >> 5;
#pragma unroll
    for (int k = 0; k < 4; k++)
        tl[ty + 8 * k][tx] = in[(size_t)(r0 + ty + 8 * k) * C + c0 + tx];
    __syncthreads();
#pragma unroll
    for (int k = 0; k < 4; k++)
        out[(size_t)(c0 + ty + 8 * k) * R + r0 + tx] = __float2half(tl[tx][ty + 8 * k]);
}

// ---------------- fp16 tensor-core GEMM core ------------------------------
#define TBK 64
#define ASTR 72
#define HG_BUF (128 * ASTR)
#define HG_SMEM (4 * HG_BUF * 2)

#define HG_LOAD(tt, bufi)                                                      \
    do {                                                                       \
        const int kb = (tt) * TBK;                                             \
        const uint32_t ao = (bufi) * (HG_BUF * 2);                             \
        const uint32_t bo = 2 * (HG_BUF * 2) + (bufi) * (HG_BUF * 2);          \
        _Pragma("unroll")                                                      \
        for (int s = 0; s < 8; s++) {                                          \
            int ch = tid + 128 * s; int row = ch >> 3, cc = ch & 7;            \
            cpa16(sb + ao + (row * ASTR + cc * 8) * 2,                         \
                  A + (size_t)(m0 + row) * K + kb + cc * 8);                   \
            int rc = n0 + row; if (rc > N - 1) rc = N - 1;                     \
            cpa16(sb + bo + (row * ASTR + cc * 8) * 2,                         \
                  Bt + (size_t)rc * K + kb + cc * 8);                          \
        }                                                                      \
        CP_COMMIT();                                                           \
    } while (0)

#define HG_BODY                                                                \
    extern __shared__ __half smh[];                                            \
    const uint32_t sb = smem_u32(smh);                                         \
    const int tid  = threadIdx.x;                                              \
    const int lane = tid & 31;                                                 \
    const int warp = tid >> 5;                                                 \
    const int wm = warp & 1;                                                   \
    const int wn = warp >> 1;                                                  \
    const int g  = lane >> 2;                                                  \
    const int tg = lane & 3;                                                   \
    const int n0 = blockIdx.x * 128;                                           \
    const int m0 = blockIdx.y * 128;                                           \
    const int lm = lane >> 3, lr8 = lane & 7;                                  \
    const int aRowOff = (lm & 1) * 8 + lr8;                                    \
    const int aKOff   = (lm >> 1) * 8;                                         \
    const int bRowOff = (lm >> 1) * 8 + lr8;                                   \
    const int bKOff   = (lm & 1) * 8;                                          \
    float acc[4][8][4];                                                        \
    _Pragma("unroll")                                                          \
    for (int i = 0; i < 4; i++)                                                \
        _Pragma("unroll")                                                      \
        for (int j = 0; j < 8; j++)                                            \
            _Pragma("unroll")                                                  \
            for (int e = 0; e < 4; e++) acc[i][j][e] = 0.f;                    \
    const int nt = K / TBK;                                                    \
    HG_LOAD(0, 0);                                                             \
    for (int t = 0; t < nt; t++) {                                             \
        const int buf = t & 1;                                                 \
        if (t + 1 < nt) { HG_LOAD(t + 1, buf ^ 1); CP_WAIT(1); }               \
        else { CP_WAIT(0); }                                                   \
        __syncthreads();                                                       \
        const uint32_t abase = sb + buf * (HG_BUF * 2);                        \
        const uint32_t bbase = sb + 2 * (HG_BUF * 2) + buf * (HG_BUF * 2);     \
        _Pragma("unroll")                                                      \
        for (int kc = 0; kc < 4; kc++) {                                       \
            unsigned af[4][4], bf[8][2];                                       \
            _Pragma("unroll")                                                  \
            for (int i = 0; i < 4; i++) {                                      \
                uint32_t a = abase + (uint32_t)(((wm * 64 + i * 16 + aRowOff) * ASTR \
                                                + kc * 16 + aKOff) * 2);       \
                ldmx4(af[i][0], af[i][1], af[i][2], af[i][3], a);              \
            }                                                                  \
            _Pragma("unroll")                                                  \
            for (int jj = 0; jj < 4; jj++) {                                   \
                uint32_t a = bbase + (uint32_t)(((wn * 64 + jj * 16 + bRowOff) * ASTR \
                                                + kc * 16 + bKOff) * 2);       \
                ldmx4(bf[2 * jj][0], bf[2 * jj][1], bf[2 * jj + 1][0], bf[2 * jj + 1][1], a); \
            }                                                                  \
            _Pragma("unroll")                                                  \
            for (int i = 0; i < 4; i++)                                        \
                _Pragma("unroll")                                              \
                for (int j = 0; j < 8; j++)                                    \
                    mma_f16(acc[i][j], af[i], bf[j]);                          \
        }                                                                      \
        __syncthreads();                                                       \
    }

__global__ __launch_bounds__(128, 2) void hgemm_k(
    const __half* __restrict__ A, const __half* __restrict__ Bt,
    float* __restrict__ C, int M, int N, int K)
{
    HG_BODY
#pragma unroll
    for (int i = 0; i < 4; i++) {
        const int r0 = m0 + wm * 64 + i * 16 + g;
#pragma unroll
        for (int j = 0; j < 8; j++) {
            const int c = n0 + wn * 64 + j * 8 + 2 * tg;
            if (c < N) {
                *(float2*)(C + (size_t)r0 * N + c) = make_float2(acc[i][j][0], acc[i][j][1]);
                *(float2*)(C + (size_t)(r0 + 8) * N + c) = make_float2(acc[i][j][2], acc[i][j][3]);
            }
        }
    }
}

__global__ __launch_bounds__(128, 2) void hgemmh_k(
    const __half* __restrict__ A, const __half* __restrict__ Bt,
    __half* __restrict__ C, int M, int N, int K)
{
    HG_BODY
#pragma unroll
    for (int i = 0; i < 4; i++) {
        const int r0 = m0 + wm * 64 + i * 16 + g;
#pragma unroll
        for (int j = 0; j < 8; j++) {
            const int c = n0 + wn * 64 + j * 8 + 2 * tg;
            if (c < N) {
                *(unsigned*)(C + (size_t)r0 * N + c) = h2u(acc[i][j][0], acc[i][j][1]);
                *(unsigned*)(C + (size_t)(r0 + 8) * N + c) = h2u(acc[i][j][2], acc[i][j][3]);
            }
        }
    }
}

// ---------------- merged RMSNorm (both slices in one launch) --------------
// blockIdx.y == 0: q slice (cols Q_RANK at offset 0 -> cqh)
// blockIdx.y == 1: kv slice (cols KV_RANK at offset Q_RANK -> kvah)
__global__ void rmsnorm2_k(const float* __restrict__ c1,
                           __half* __restrict__ cqh, __half* __restrict__ kvah,
                           const float* __restrict__ wq, const float* __restrict__ wkv)
{
    const int row = blockIdx.x;
    const int which = blockIdx.y;
    const int cols = which ? KV_RANK : Q_RANK;
    const float* xi = c1 + (size_t)row * N1 + (which ? Q_RANK : 0);
    const float* w = which ? wkv : wq;
    __half* yo = (which ? kvah + (size_t)row * KV_RANK : cqh + (size_t)row * Q_RANK);

    float s = 0.f;
    for (int c = threadIdx.x; c < cols; c += blockDim.x) {
        float v = xi[c];
        s += v * v;
    }
    __shared__ float red[8];
#pragma unroll
    for (int o = 16; o > 0; o >>= 1) s += __shfl_down_sync(0xffffffffu, s, o);
    int warp = threadIdx.x >> 5, lane = threadIdx.x & 31;
    if (lane == 0) red[warp] = s;
    __syncthreads();
    if (warp == 0) {
        s = (lane < (blockDim.x >> 5)) ? red[lane] : 0.f;
#pragma unroll
        for (int o = 4; o > 0; o >>= 1) s += __shfl_down_sync(0xffffffffu, s, o);
        if (lane == 0) red[0] = s;
    }
    __syncthreads();
    float r = rsqrtf(red[0] / (float)cols + 1e-6f);
    for (int c = threadIdx.x; c < cols; c += blockDim.x)
        yo[c] = __float2half(xi[c] * r * w[c]);
}

// ---------------- RoPE ---------------------------------------------------
__global__ void rope_table_k(float* ct, float* st)
{
    int s = blockIdx.x, i = threadIdx.x;
    double inv = exp(-((double)(2 * i) / 64.0) * log(10000.0));
    double ang = (double)s * inv;
    ct[s * 32 + i] = (float)cos(ang);
    st[s * 32 + i] = (float)sin(ang);
}

// RoPE: fp32 pe slice (strided source) -> half kpe
__global__ void rope_kh_k(const float* __restrict__ PE, int pe_stride, __half* KPE,
                          const float* __restrict__ ct, const float* __restrict__ st)
{
    int bs = blockIdx.x;
    int s = bs & (SS - 1);
    int i = threadIdx.x;
    const float* src = PE + (size_t)bs * pe_stride;
    float c = ct[s * 32 + i], sn = st[s * 32 + i];
    float x1 = src[i], x2 = src[32 + i];
    KPE[(size_t)bs * ROPE_D + i]      = __float2half(x1 * c - x2 * sn);
    KPE[(size_t)bs * ROPE_D + 32 + i] = __float2half(x2 * c + x1 * sn);
}

// ---------------- fp16 flash attention with fused q-RoPE ------------------
#define FBM 128
#define FBN 64
#define KSTR 200
#define VSTR 136
#define KELE (FBN * KSTR)
#define VELE (FBN * VSTR)
#define FLASH_SMEM (2 * (KELE + VELE) * 2)

__global__ __launch_bounds__(256) void flash_k(
    const __half* __restrict__ QH_g, const __half* __restrict__ KVH_g,
    const __half* __restrict__ KPEH_g, __half* __restrict__ OH,
    const float* __restrict__ ct, const float* __restrict__ st)
{
    extern __shared__ __half smf[];
    const uint32_t sbase = smem_u32(smf);

    const int q0 = blockIdx.x * FBM;
    const int h = blockIdx.y;
    const int b = blockIdx.z;
    const int t = threadIdx.x;
    const int warp = t >> 5;
    const int lane = t & 31;
    const int g = lane >> 2;
    const int tg = lane & 3;
    const int row0 = warp * 16 + g;
    const float scale = rsqrtf((float)QH);

    const int lm = lane >> 3, lr8 = lane & 7;
    const int kRowOff = (lm >> 1) * 8 + lr8;
    const int kKOff   = (lm & 1) * 8;
    const int vK      = (lm & 1) * 8 + lr8;
    const int vC      = (lm >> 1) * 8;

    // persistent Q A-frags, with RoPE applied in registers to the pe slice
    unsigned aq[12][4];
    {
        const unsigned* qp0 = (const unsigned*)(QH_g + ((size_t)(b * SS + q0 + row0) * HH + h) * QH);
        const unsigned* qp1 = qp0 + (size_t)8 * HH * QH / 2;
#pragma unroll
        for (int kc = 0; kc < 12; kc++) {
            aq[kc][0] = qp0[kc * 8 + tg];
            aq[kc][1] = qp1[kc * 8 + tg];
            aq[kc][2] = qp0[kc * 8 + tg + 4];
            aq[kc][3] = qp1[kc * 8 + tg + 4];
        }
        // RoPE rotate: pe cols are kc 8..11 (global cols 128..191).
        // Pair (i, i+32): kc in {8,9} pairs with kc+2, same word slot.
        const int s0 = q0 + row0;          // row for slots 0,2
        const int s1 = s0 + 8;             // row for slots 1,3
#pragma unroll
        for (int kc8 = 8; kc8 < 10; kc8++) {
#pragma unroll
            for (int j = 0; j < 4; j++) {
                const int srow = (j & 1) ? s1 : s0;
                const int i = (kc8 - 8) * 16 + ((j >> 1) ? 8 : 0) + 2 * tg;
                float c0 = ct[srow * 32 + i],     sn0 = st[srow * 32 + i];
                float c1 = ct[srow * 32 + i + 1], sn1 = st[srow * 32 + i + 1];
                __half2 x1h = *(__half2*)&aq[kc8][j];
                __half2 x2h = *(__half2*)&aq[kc8 + 2][j];
                float x1a = __half2float(x1h.x), x1b = __half2float(x1h.y);
                float x2a = __half2float(x2h.x), x2b = __half2float(x2h.y);
                aq[kc8][j]     = h2u(x1a * c0 - x2a * sn0, x1b * c1 - x2b * sn1);
                aq[kc8 + 2][j] = h2u(x2a * c0 + x1a * sn0, x2b * c1 + x1b * sn1);
            }
        }
    }

    float oacc[16][4];
#pragma unroll
    for (int i = 0; i < 16; i++)
#pragma unroll
        for (int e = 0; e < 4; e++) oacc[i][e] = 0.f;
    float m0 = -3.0e38f, m1 = -3.0e38f, l0 = 0.f, l1 = 0.f;

    const int flr = t >> 2;
    const int q4 = t & 3;
    const int ntiles = (q0 + FBM) / FBN;

#define FL_LOAD(tt, bufi)                                                          \
    do {                                                                           \
        const int kk0 = (tt) * FBN;                                                \
        const __half* kvrow = KVH_g + ((size_t)(b * SS + kk0 + flr) * HH + h) * KVH;\
        const __half* kprow = KPEH_g + (size_t)(b * SS + kk0 + flr) * ROPE_D;      \
        const uint32_t kdst = sbase + (bufi) * (KELE * 2) + flr * (KSTR * 2);      \
        const uint32_t vdst = sbase + 2 * (KELE * 2) + (bufi) * (VELE * 2)         \
                              + flr * (VSTR * 2);                                  \
        _Pragma("unroll")                                                          \
        for (int i = 0; i < 6; i++) {                                              \
            int c = q4 * 6 + i;                                                    \
            const __half* src = (c < 16) ? kvrow + c * 8 : kprow + (c - 16) * 8;   \
            cpa16(kdst + c * 16, src);                                             \
        }                                                                          \
        _Pragma("unroll")                                                          \
        for (int i = 0; i < 4; i++) {                                              \
            int c = q4 * 4 + i;                                                    \
            cpa16(vdst + c * 16, kvrow + 128 + c * 8);                             \
        }                                                                          \
        CP_COMMIT();                                                               \
    } while (0)

    FL_LOAD(0, 0);

    for (int tile = 0; tile < ntiles; tile++) {
        const int k0 = tile * FBN;
        const int buf = tile & 1;
        if (tile + 1 < ntiles) {
            FL_LOAD(tile + 1, buf ^ 1);
            CP_WAIT(1);
        } else {
            CP_WAIT(0);
        }
        __syncthreads();

        if (k0 <= q0 + warp * 16 + 15) {
            const uint32_t kb2 = sbase + buf * (KELE * 2);
            const uint32_t vb = sbase + 2 * (KELE * 2) + buf * (VELE * 2);

            float c[8][4];
#pragma unroll
            for (int nb = 0; nb < 8; nb++)
#pragma unroll
                for (int e = 0; e < 4; e++) c[nb][e] = 0.f;
#pragma unroll
            for (int kc = 0; kc < 12; kc++) {
#pragma unroll
                for (int n16 = 0; n16 < 4; n16++) {
                    uint32_t a = kb2 + (uint32_t)(((n16 * 16 + kRowOff) * KSTR
                                                  + kc * 16 + kKOff) * 2);
                    unsigned b0, b1, b2, b3;
                    ldmx4(b0, b1, b2, b3, a);
                    unsigned bf0[2] = {b0, b1};
                    unsigned bf1[2] = {b2, b3};
                    mma_f16(c[2 * n16], aq[kc], bf0);
                    mma_f16(c[2 * n16 + 1], aq[kc], bf1);
                }
            }
#pragma unroll
            for (int nb = 0; nb < 8; nb++)
#pragma unroll
                for (int e = 0; e < 4; e++) c[nb][e] *= scale;

            if (k0 + FBN - 1 > q0 + warp * 16) {
                const int r0g = q0 + warp * 16 + g;
#pragma unroll
                for (int nb = 0; nb < 8; nb++) {
                    int col = k0 + nb * 8 + 2 * tg;
                    if (col     > r0g)     c[nb][0] = -3.0e38f;
                    if (col + 1 > r0g)     c[nb][1] = -3.0e38f;
                    if (col     > r0g + 8) c[nb][2] = -3.0e38f;
                    if (col + 1 > r0g + 8) c[nb][3] = -3.0e38f;
                }
            }

            float tm0 = -3.0e38f, tm1 = -3.0e38f;
#pragma unroll
            for (int nb = 0; nb < 8; nb++) {
                tm0 = fmaxf(tm0, fmaxf(c[nb][0], c[nb][1]));
                tm1 = fmaxf(tm1, fmaxf(c[nb][2], c[nb][3]));
            }
            tm0 = fmaxf(tm0, __shfl_xor_sync(0xffffffffu, tm0, 1));
            tm0 = fmaxf(tm0, __shfl_xor_sync(0xffffffffu, tm0, 2));
            tm1 = fmaxf(tm1, __shfl_xor_sync(0xffffffffu, tm1, 1));
            tm1 = fmaxf(tm1, __shfl_xor_sync(0xffffffffu, tm1, 2));

            float nm0 = fmaxf(m0, tm0), nm1 = fmaxf(m1, tm1);
            float co0 = __expf(m0 - nm0), co1 = __expf(m1 - nm1);
            l0 *= co0; l1 *= co1;
#pragma unroll
            for (int nb = 0; nb < 16; nb++) {
                oacc[nb][0] *= co0; oacc[nb][1] *= co0;
                oacc[nb][2] *= co1; oacc[nb][3] *= co1;
            }
            m0 = nm0; m1 = nm1;

            float ls0 = 0.f, ls1 = 0.f;
#pragma unroll
            for (int nb = 0; nb < 8; nb++) {
                c[nb][0] = __expf(c[nb][0] - nm0);
                c[nb][1] = __expf(c[nb][1] - nm0);
                c[nb][2] = __expf(c[nb][2] - nm1);
                c[nb][3] = __expf(c[nb][3] - nm1);
                ls0 += c[nb][0] + c[nb][1];
                ls1 += c[nb][2] + c[nb][3];
            }
            ls0 += __shfl_xor_sync(0xffffffffu, ls0, 1);
            ls0 += __shfl_xor_sync(0xffffffffu, ls0, 2);
            ls1 += __shfl_xor_sync(0xffffffffu, ls1, 1);
            ls1 += __shfl_xor_sync(0xffffffffu, ls1, 2);
            l0 += ls0; l1 += ls1;

#pragma unroll
            for (int kr = 0; kr < 4; kr++) {
                unsigned ap[4];
                ap[0] = h2u(c[2 * kr][0],     c[2 * kr][1]);
                ap[1] = h2u(c[2 * kr][2],     c[2 * kr][3]);
                ap[2] = h2u(c[2 * kr + 1][0], c[2 * kr + 1][1]);
                ap[3] = h2u(c[2 * kr + 1][2], c[2 * kr + 1][3]);
                const uint32_t krowb = vb + (uint32_t)((kr * 16 + vK) * (VSTR * 2));
#pragma unroll
                for (int np = 0; np < 8; np++) {
                    uint32_t a = krowb + (uint32_t)((np * 16 + vC) * 2);
                    unsigned b0, b1, b2, b3;
                    ldmx4t(b0, b1, b2, b3, a);
                    unsigned bv0[2] = {b0, b1};
                    unsigned bv1[2] = {b2, b3};
                    mma_f16(oacc[2 * np], ap, bv0);
                    mma_f16(oacc[2 * np + 1], ap, bv1);
                }
            }
        }
        __syncthreads();
    }

    float inv0 = 1.f / l0, inv1 = 1.f / l1;
    __half* o0 = OH + ((size_t)(b * SS + q0 + row0) * HH + h) * VD;
    __half* o1 = o0 + (size_t)8 * HH * VD;
#pragma unroll
    for (int nb = 0; nb < 16; nb++) {
        *(unsigned*)(o0 + nb * 8 + 2 * tg) = h2u(oacc[nb][0] * inv0, oacc[nb][1] * inv0);
        *(unsigned*)(o1 + nb * 8 + 2 * tg) = h2u(oacc[nb][2] * inv1, oacc[nb][3] * inv1);
    }
}

// ---------------- host launcher ------------------------------------------
extern "C" void kernel_launch(void* const* d_in, const int* in_sizes, int n_in,
                              void* d_out, int out_size)
{
    const float* x         = (const float*)d_in[0];
    const float* w_dq      = (const float*)d_in[1];
    const float* q_a_norm  = (const float*)d_in[2];
    const float* w_uq      = (const float*)d_in[3];
    const float* w_dkv     = (const float*)d_in[4];
    const float* kv_a_norm = (const float*)d_in[5];
    const float* w_ukv     = (const float*)d_in[6];
    const float* w_o       = (const float*)d_in[7];
    float* out = (float*)d_out;

    float *c1, *ct, *st;
    __half *xh, *w1T, *wuqT, *wukvT, *woT, *cqh, *kvah, *oh, *qh, *kvh, *kpeh;
    cudaGetSymbolAddress((void**)&c1,  g_c1);
    cudaGetSymbolAddress((void**)&ct,  g_cos);
    cudaGetSymbolAddress((void**)&st,  g_sin);
    cudaGetSymbolAddress((void**)&xh,    g_xh);
    cudaGetSymbolAddress((void**)&w1T,   g_w1T);
    cudaGetSymbolAddress((void**)&wuqT,  g_wuqT);
    cudaGetSymbolAddress((void**)&wukvT, g_wukvT);
    cudaGetSymbolAddress((void**)&woT,   g_woT);
    cudaGetSymbolAddress((void**)&cqh,   g_cqh);
    cudaGetSymbolAddress((void**)&kvah,  g_kvah);
    cudaGetSymbolAddress((void**)&oh,    g_oh);
    cudaGetSymbolAddress((void**)&qh,    g_qh);
    cudaGetSymbolAddress((void**)&kvh,   g_kvh);
    cudaGetSymbolAddress((void**)&kpeh,  g_kpeh);

    cudaFuncSetAttribute(hgemm_k,  cudaFuncAttributeMaxDynamicSharedMemorySize, HG_SMEM);
    cudaFuncSetAttribute(hgemmh_k, cudaFuncAttributeMaxDynamicSharedMemorySize, HG_SMEM);
    cudaFuncSetAttribute(flash_k,  cudaFuncAttributeMaxDynamicSharedMemorySize, FLASH_SMEM);

    // launches 1-5: converts needed by the c1 GEMM and up-projections
    cvth_k<<<592, 256>>>((const float4*)x, xh, RTOT * DD / 4);
    trth_k<<<dim3(Q_RANK / 32, DD / 32), 256>>>(w_dq, w1T, DD, Q_RANK);
    trth_k<<<dim3((KV_RANK + ROPE_D) / 32, DD / 32), 256>>>(
        w_dkv, w1T + (size_t)Q_RANK * DD, DD, KV_RANK + ROPE_D);
    trth_k<<<dim3((HH * QH) / 32, Q_RANK / 32), 256>>>(w_uq, wuqT, Q_RANK, HH * QH);
    trth_k<<<dim3((HH * KVH) / 32, KV_RANK / 32), 256>>>(w_ukv, wukvT, KV_RANK, HH * KVH);

    // launch 6 (ncu -s 5 profiles this): merged x-projection
    hgemm_k<<<dim3((N1 + 127) / 128, RTOT / 128), 128, HG_SMEM>>>(xh, w1T, c1, RTOT, N1, DD);

    // both norms in one launch
    rmsnorm2_k<<<dim3(RTOT, 2), 256>>>(c1, cqh, kvah, q_a_norm, kv_a_norm);

    // up-projections (fp16 out)
    hgemmh_k<<<dim3((HH * QH) / 128, RTOT / 128), 128, HG_SMEM>>>(cqh, wuqT, qh, RTOT, HH * QH, Q_RANK);
    hgemmh_k<<<dim3((HH * KVH) / 128, RTOT / 128), 128, HG_SMEM>>>(kvah, wukvT, kvh, RTOT, HH * KVH, KV_RANK);

    // RoPE table + k_pe; w_o transpose (needed only by final GEMM)
    rope_table_k<<<SS, 32>>>(ct, st);
    rope_kh_k<<<RTOT, 32>>>(c1 + Q_RANK + KV_RANK, N1, kpeh, ct, st);
    trth_k<<<dim3(DD / 32, (HH * VD) / 32), 256>>>(w_o, woT, HH * VD, DD);

    // attention (q-RoPE fused into the Q fragment load)
    flash_k<<<dim3(SS / FBM, HH, BB), 256, FLASH_SMEM>>>(qh, kvh, kpeh, oh, ct, st);

    // output projection
    hgemm_k<<<dim3(DD / 128, RTOT / 128), 128, HG_SMEM>>>(oh, woT, out, RTOT, DD, HH * VD);
}

// round 17
// speedup vs baseline: 1.5136x; 1.5136x over previous
#include <cuda_runtime.h>
#include <cuda_fp16.h>
#include <math.h>
#include <stdint.h>

// Problem constants
#define BB 2
#define SS 2048
#define DD 2048
#define HH 16
#define NOPE 128
#define ROPE_D 64
#define VD 128
#define KV_RANK 512
#define Q_RANK 1536
#define QH (NOPE + ROPE_D)   // 192
#define KVH (NOPE + VD)      // 256
#define RTOT (BB * SS)       // 4096 rows
#define N1 (Q_RANK + KV_RANK + ROPE_D)   // 2112

// ---------------- scratch (device globals, no allocation) ----------------
__device__ float g_c1 [RTOT * N1];
__device__ float g_cos[SS * (ROPE_D / 2)];
__device__ float g_sin[SS * (ROPE_D / 2)];
__device__ __half g_xh  [RTOT * DD];
__device__ __half g_w1T [N1 * DD];
__device__ __half g_wuqT [HH * QH * Q_RANK];
__device__ __half g_wukvT[HH * KVH * KV_RANK];
__device__ __half g_woT  [DD * HH * VD];
__device__ __half g_cqh [RTOT * Q_RANK];
__device__ __half g_kvah[RTOT * KV_RANK];
__device__ __half g_oh  [RTOT * (HH * VD)];
__device__ __half g_qh  [RTOT * (HH * QH)];
__device__ __half g_kvh [RTOT * (HH * KVH)];
__device__ __half g_kpeh[RTOT * ROPE_D];

// ---------------- helpers -------------------------------------------------
__device__ __forceinline__ unsigned h2u(float a, float b) {
    __half2 h = __floats2half2_rn(a, b);
    return *(unsigned*)&h;
}

__device__ __forceinline__ void mma_f16(float c[4], const unsigned a[4], const unsigned b[2]) {
    asm volatile(
        "mma.sync.aligned.m16n8k16.row.col.f32.f16.f16.f32 "
        "{%0,%1,%2,%3}, {%4,%5,%6,%7}, {%8,%9}, {%0,%1,%2,%3};\n"
        : "+f"(c[0]), "+f"(c[1]), "+f"(c[2]), "+f"(c[3])
        : "r"(a[0]), "r"(a[1]), "r"(a[2]), "r"(a[3]), "r"(b[0]), "r"(b[1]));
}

__device__ __forceinline__ void ldmx4(unsigned& d0, unsigned& d1, unsigned& d2,
                                      unsigned& d3, uint32_t a) {
    asm volatile("ldmatrix.sync.aligned.m8n8.x4.shared.b16 {%0,%1,%2,%3}, [%4];"
                 : "=r"(d0), "=r"(d1), "=r"(d2), "=r"(d3) : "r"(a));
}
__device__ __forceinline__ void ldmx4t(unsigned& d0, unsigned& d1, unsigned& d2,
                                       unsigned& d3, uint32_t a) {
    asm volatile("ldmatrix.sync.aligned.m8n8.x4.trans.shared.b16 {%0,%1,%2,%3}, [%4];"
                 : "=r"(d0), "=r"(d1), "=r"(d2), "=r"(d3) : "r"(a));
}

__device__ __forceinline__ void cpa16(uint32_t dst_smem, const void* src) {
    asm volatile("cp.async.cg.shared.global [%0], [%1], 16;\n" :: "r"(dst_smem), "l"(src));
}
#define CP_COMMIT() asm volatile("cp.async.commit_group;\n")
#define CP_WAIT(n)  asm volatile("cp.async.wait_group %0;\n" :: "n"(n))

__device__ __forceinline__ uint32_t smem_u32(const void* p) {
    uint32_t a;
    asm("{ .reg .u64 t; cvta.to.shared.u64 t, %1; cvt.u32.u64 %0, t; }" : "=r"(a) : "l"(p));
    return a;
}

// ---------------- fp32 -> fp16 linear convert -----------------------------
__global__ void cvth_k(const float4* __restrict__ in, __half* __restrict__ out, int n4)
{
    int i = blockIdx.x * blockDim.x + threadIdx.x;
    int stride = gridDim.x * blockDim.x;
    for (; i < n4; i += stride) {
        float4 v = in[i];
        uint2 w;
        w.x = h2u(v.x, v.y);
        w.y = h2u(v.z, v.w);
        *(uint2*)(out + (size_t)i * 4) = w;
    }
}

// ---------------- transpose + fp16: in[R][C] fp32 -> out[C][R] half -------
__global__ __launch_bounds__(256) void trth_k(const float* __restrict__ in,
                                              __half* __restrict__ out, int R, int C)
{
    __shared__ float tl[32][33];
    int c0 = blockIdx.x * 32, r0 = blockIdx.y * 32;
    int tx = threadIdx.x & 31, ty = threadIdx.x >> 5;
#pragma unroll
    for (int k = 0; k < 4; k++)
        tl[ty + 8 * k][tx] = in[(size_t)(r0 + ty + 8 * k) * C + c0 + tx];
    __syncthreads();
#pragma unroll
    for (int k = 0; k < 4; k++)
        out[(size_t)(c0 + ty + 8 * k) * R + r0 + tx] = __float2half(tl[tx][ty + 8 * k]);
}

// ---------------- fp16 tensor-core GEMM core ------------------------------
#define TBK 64
#define ASTR 72
#define HG_BUF (128 * ASTR)
#define HG_SMEM (4 * HG_BUF * 2)

#define HG_LOAD(tt, bufi)                                                      \
    do {                                                                       \
        const int kb = (tt) * TBK;                                             \
        const uint32_t ao = (bufi) * (HG_BUF * 2);                             \
        const uint32_t bo = 2 * (HG_BUF * 2) + (bufi) * (HG_BUF * 2);          \
        _Pragma("unroll")                                                      \
        for (int s = 0; s < 8; s++) {                                          \
            int ch = tid + 128 * s; int row = ch >> 3, cc = ch & 7;            \
            cpa16(sb + ao + (row * ASTR + cc * 8) * 2,                         \
                  A + (size_t)(m0 + row) * K + kb + cc * 8);                   \
            int rc = n0 + row; if (rc > N - 1) rc = N - 1;                     \
            cpa16(sb + bo + (row * ASTR + cc * 8) * 2,                         \
                  Bt + (size_t)rc * K + kb + cc * 8);                          \
        }                                                                      \
        CP_COMMIT();                                                           \
    } while (0)

#define HG_BODY                                                                \
    extern __shared__ __half smh[];                                            \
    const uint32_t sb = smem_u32(smh);                                         \
    const int tid  = threadIdx.x;                                              \
    const int lane = tid & 31;                                                 \
    const int warp = tid >> 5;                                                 \
    const int wm = warp & 1;                                                   \
    const int wn = warp >> 1;                                                  \
    const int g  = lane >> 2;                                                  \
    const int tg = lane & 3;                                                   \
    const int n0 = blockIdx.x * 128;                                           \
    const int m0 = blockIdx.y * 128;                                           \
    const int lm = lane >> 3, lr8 = lane & 7;                                  \
    const int aRowOff = (lm & 1) * 8 + lr8;                                    \
    const int aKOff   = (lm >> 1) * 8;                                         \
    const int bRowOff = (lm >> 1) * 8 + lr8;                                   \
    const int bKOff   = (lm & 1) * 8;                                          \
    float acc[4][8][4];                                                        \
    _Pragma("unroll")                                                          \
    for (int i = 0; i < 4; i++)                                                \
        _Pragma("unroll")                                                      \
        for (int j = 0; j < 8; j++)                                            \
            _Pragma("unroll")                                                  \
            for (int e = 0; e < 4; e++) acc[i][j][e] = 0.f;                    \
    const int nt = K / TBK;                                                    \
    HG_LOAD(0, 0);                                                             \
    for (int t = 0; t < nt; t++) {                                             \
        const int buf = t & 1;                                                 \
        if (t + 1 < nt) { HG_LOAD(t + 1, buf ^ 1); CP_WAIT(1); }               \
        else { CP_WAIT(0); }                                                   \
        __syncthreads();                                                       \
        const uint32_t abase = sb + buf * (HG_BUF * 2);                        \
        const uint32_t bbase = sb + 2 * (HG_BUF * 2) + buf * (HG_BUF * 2);     \
        _Pragma("unroll")                                                      \
        for (int kc = 0; kc < 4; kc++) {                                       \
            unsigned af[4][4], bf[8][2];                                       \
            _Pragma("unroll")                                                  \
            for (int i = 0; i < 4; i++) {                                      \
                uint32_t a = abase + (uint32_t)(((wm * 64 + i * 16 + aRowOff) * ASTR \
                                                + kc * 16 + aKOff) * 2);       \
                ldmx4(af[i][0], af[i][1], af[i][2], af[i][3], a);              \
            }                                                                  \
            _Pragma("unroll")                                                  \
            for (int jj = 0; jj < 4; jj++) {                                   \
                uint32_t a = bbase + (uint32_t)(((wn * 64 + jj * 16 + bRowOff) * ASTR \
                                                + kc * 16 + bKOff) * 2);       \
                ldmx4(bf[2 * jj][0], bf[2 * jj][1], bf[2 * jj + 1][0], bf[2 * jj + 1][1], a); \
            }                                                                  \
            _Pragma("unroll")                                                  \
            for (int i = 0; i < 4; i++)                                        \
                _Pragma("unroll")                                              \
                for (int j = 0; j < 8; j++)                                    \
                    mma_f16(acc[i][j], af[i], bf[j]);                          \
        }                                                                      \
        __syncthreads();                                                       \
    }

__global__ __launch_bounds__(128, 2) void hgemm_k(
    const __half* __restrict__ A, const __half* __restrict__ Bt,
    float* __restrict__ C, int M, int N, int K)
{
    HG_BODY
#pragma unroll
    for (int i = 0; i < 4; i++) {
        const int r0 = m0 + wm * 64 + i * 16 + g;
#pragma unroll
        for (int j = 0; j < 8; j++) {
            const int c = n0 + wn * 64 + j * 8 + 2 * tg;
            if (c < N) {
                *(float2*)(C + (size_t)r0 * N + c) = make_float2(acc[i][j][0], acc[i][j][1]);
                *(float2*)(C + (size_t)(r0 + 8) * N + c) = make_float2(acc[i][j][2], acc[i][j][3]);
            }
        }
    }
}

__global__ __launch_bounds__(128, 2) void hgemmh_k(
    const __half* __restrict__ A, const __half* __restrict__ Bt,
    __half* __restrict__ C, int M, int N, int K)
{
    HG_BODY
#pragma unroll
    for (int i = 0; i < 4; i++) {
        const int r0 = m0 + wm * 64 + i * 16 + g;
#pragma unroll
        for (int j = 0; j < 8; j++) {
            const int c = n0 + wn * 64 + j * 8 + 2 * tg;
            if (c < N) {
                *(unsigned*)(C + (size_t)r0 * N + c) = h2u(acc[i][j][0], acc[i][j][1]);
                *(unsigned*)(C + (size_t)(r0 + 8) * N + c) = h2u(acc[i][j][2], acc[i][j][3]);
            }
        }
    }
}

// ---------------- merged RMSNorm (both slices in one launch) --------------
__global__ void rmsnorm2_k(const float* __restrict__ c1,
                           __half* __restrict__ cqh, __half* __restrict__ kvah,
                           const float* __restrict__ wq, const float* __restrict__ wkv)
{
    const int row = blockIdx.x;
    const int which = blockIdx.y;
    const int cols = which ? KV_RANK : Q_RANK;
    const float* xi = c1 + (size_t)row * N1 + (which ? Q_RANK : 0);
    const float* w = which ? wkv : wq;
    __half* yo = (which ? kvah + (size_t)row * KV_RANK : cqh + (size_t)row * Q_RANK);

    float s = 0.f;
    for (int c = threadIdx.x; c < cols; c += blockDim.x) {
        float v = xi[c];
        s += v * v;
    }
    __shared__ float red[8];
#pragma unroll
    for (int o = 16; o > 0; o >>= 1) s += __shfl_down_sync(0xffffffffu, s, o);
    int warp = threadIdx.x >> 5, lane = threadIdx.x & 31;
    if (lane == 0) red[warp] = s;
    __syncthreads();
    if (warp == 0) {
        s = (lane < (blockDim.x >> 5)) ? red[lane] : 0.f;
#pragma unroll
        for (int o = 4; o > 0; o >>= 1) s += __shfl_down_sync(0xffffffffu, s, o);
        if (lane == 0) red[0] = s;
    }
    __syncthreads();
    float r = rsqrtf(red[0] / (float)cols + 1e-6f);
    for (int c = threadIdx.x; c < cols; c += blockDim.x)
        yo[c] = __float2half(xi[c] * r * w[c]);
}

// ---------------- RoPE ---------------------------------------------------
__global__ void rope_table_k(float* ct, float* st)
{
    int s = blockIdx.x, i = threadIdx.x;
    double inv = exp(-((double)(2 * i) / 64.0) * log(10000.0));
    double ang = (double)s * inv;
    ct[s * 32 + i] = (float)cos(ang);
    st[s * 32 + i] = (float)sin(ang);
}

// RoPE in-place on half q (pe slice of each head)
__global__ void rope_qh_k(__half* Q, const float* __restrict__ ct, const float* __restrict__ st)
{
    int bs = blockIdx.x;
    int s = bs & (SS - 1);
    int i = threadIdx.x;
    int h = threadIdx.y;
    size_t base = ((size_t)bs * HH + h) * QH + NOPE;
    float c = ct[s * 32 + i], sn = st[s * 32 + i];
    float x1 = __half2float(Q[base + i]), x2 = __half2float(Q[base + 32 + i]);
    Q[base + i]      = __float2half(x1 * c - x2 * sn);
    Q[base + 32 + i] = __float2half(x2 * c + x1 * sn);
}

// RoPE: fp32 pe slice (strided source) -> half kpe
__global__ void rope_kh_k(const float* __restrict__ PE, int pe_stride, __half* KPE,
                          const float* __restrict__ ct, const float* __restrict__ st)
{
    int bs = blockIdx.x;
    int s = bs & (SS - 1);
    int i = threadIdx.x;
    const float* src = PE + (size_t)bs * pe_stride;
    float c = ct[s * 32 + i], sn = st[s * 32 + i];
    float x1 = src[i], x2 = src[32 + i];
    KPE[(size_t)bs * ROPE_D + i]      = __float2half(x1 * c - x2 * sn);
    KPE[(size_t)bs * ROPE_D + 32 + i] = __float2half(x2 * c + x1 * sn);
}

// ---------------- fp16 tensor-core causal flash attention -----------------
#define FBM 128
#define FBN 64
#define KSTR 200
#define VSTR 136
#define KELE (FBN * KSTR)
#define VELE (FBN * VSTR)
#define FLASH_SMEM (2 * (KELE + VELE) * 2)

__global__ __launch_bounds__(256) void flash_k(
    const __half* __restrict__ QH_g, const __half* __restrict__ KVH_g,
    const __half* __restrict__ KPEH_g, __half* __restrict__ OH)
{
    extern __shared__ __half smf[];
    const uint32_t sbase = smem_u32(smf);

    const int q0 = blockIdx.x * FBM;
    const int h = blockIdx.y;
    const int b = blockIdx.z;
    const int t = threadIdx.x;
    const int warp = t >> 5;
    const int lane = t & 31;
    const int g = lane >> 2;
    const int tg = lane & 3;
    const int row0 = warp * 16 + g;
    const float scale = rsqrtf((float)QH);

    const int lm = lane >> 3, lr8 = lane & 7;
    const int kRowOff = (lm >> 1) * 8 + lr8;
    const int kKOff   = (lm & 1) * 8;
    const int vK      = (lm & 1) * 8 + lr8;
    const int vC      = (lm >> 1) * 8;

    unsigned aq[12][4];
    {
        const unsigned* qp0 = (const unsigned*)(QH_g + ((size_t)(b * SS + q0 + row0) * HH + h) * QH);
        const unsigned* qp1 = qp0 + (size_t)8 * HH * QH / 2;
#pragma unroll
        for (int kc = 0; kc < 12; kc++) {
            aq[kc][0] = qp0[kc * 8 + tg];
            aq[kc][1] = qp1[kc * 8 + tg];
            aq[kc][2] = qp0[kc * 8 + tg + 4];
            aq[kc][3] = qp1[kc * 8 + tg + 4];
        }
    }

    float oacc[16][4];
#pragma unroll
    for (int i = 0; i < 16; i++)
#pragma unroll
        for (int e = 0; e < 4; e++) oacc[i][e] = 0.f;
    float m0 = -3.0e38f, m1 = -3.0e38f, l0 = 0.f, l1 = 0.f;

    const int flr = t >> 2;
    const int q4 = t & 3;
    const int ntiles = (q0 + FBM) / FBN;

#define FL_LOAD(tt, bufi)                                                          \
    do {                                                                           \
        const int kk0 = (tt) * FBN;                                                \
        const __half* kvrow = KVH_g + ((size_t)(b * SS + kk0 + flr) * HH + h) * KVH;\
        const __half* kprow = KPEH_g + (size_t)(b * SS + kk0 + flr) * ROPE_D;      \
        const uint32_t kdst = sbase + (bufi) * (KELE * 2) + flr * (KSTR * 2);      \
        const uint32_t vdst = sbase + 2 * (KELE * 2) + (bufi) * (VELE * 2)         \
                              + flr * (VSTR * 2);                                  \
        _Pragma("unroll")                                                          \
        for (int i = 0; i < 6; i++) {                                              \
            int c = q4 * 6 + i;                                                    \
            const __half* src = (c < 16) ? kvrow + c * 8 : kprow + (c - 16) * 8;   \
            cpa16(kdst + c * 16, src);                                             \
        }                                                                          \
        _Pragma("unroll")                                                          \
        for (int i = 0; i < 4; i++) {                                              \
            int c = q4 * 4 + i;                                                    \
            cpa16(vdst + c * 16, kvrow + 128 + c * 8);                             \
        }                                                                          \
        CP_COMMIT();                                                               \
    } while (0)

    FL_LOAD(0, 0);

    for (int tile = 0; tile < ntiles; tile++) {
        const int k0 = tile * FBN;
        const int buf = tile & 1;
        if (tile + 1 < ntiles) {
            FL_LOAD(tile + 1, buf ^ 1);
            CP_WAIT(1);
        } else {
            CP_WAIT(0);
        }
        __syncthreads();

        if (k0 <= q0 + warp * 16 + 15) {
            const uint32_t kb2 = sbase + buf * (KELE * 2);
            const uint32_t vb = sbase + 2 * (KELE * 2) + buf * (VELE * 2);

            float c[8][4];
#pragma unroll
            for (int nb = 0; nb < 8; nb++)
#pragma unroll
                for (int e = 0; e < 4; e++) c[nb][e] = 0.f;
#pragma unroll
            for (int kc = 0; kc < 12; kc++) {
#pragma unroll
                for (int n16 = 0; n16 < 4; n16++) {
                    uint32_t a = kb2 + (uint32_t)(((n16 * 16 + kRowOff) * KSTR
                                                  + kc * 16 + kKOff) * 2);
                    unsigned b0, b1, b2, b3;
                    ldmx4(b0, b1, b2, b3, a);
                    unsigned bf0[2] = {b0, b1};
                    unsigned bf1[2] = {b2, b3};
                    mma_f16(c[2 * n16], aq[kc], bf0);
                    mma_f16(c[2 * n16 + 1], aq[kc], bf1);
                }
            }
#pragma unroll
            for (int nb = 0; nb < 8; nb++)
#pragma unroll
                for (int e = 0; e < 4; e++) c[nb][e] *= scale;

            if (k0 + FBN - 1 > q0 + warp * 16) {
                const int r0g = q0 + warp * 16 + g;
#pragma unroll
                for (int nb = 0; nb < 8; nb++) {
                    int col = k0 + nb * 8 + 2 * tg;
                    if (col     > r0g)     c[nb][0] = -3.0e38f;
                    if (col + 1 > r0g)     c[nb][1] = -3.0e38f;
                    if (col     > r0g + 8) c[nb][2] = -3.0e38f;
                    if (col + 1 > r0g + 8) c[nb][3] = -3.0e38f;
                }
            }

            float tm0 = -3.0e38f, tm1 = -3.0e38f;
#pragma unroll
            for (int nb = 0; nb < 8; nb++) {
                tm0 = fmaxf(tm0, fmaxf(c[nb][0], c[nb][1]));
                tm1 = fmaxf(tm1, fmaxf(c[nb][2], c[nb][3]));
            }
            tm0 = fmaxf(tm0, __shfl_xor_sync(0xffffffffu, tm0, 1));
            tm0 = fmaxf(tm0, __shfl_xor_sync(0xffffffffu, tm0, 2));
            tm1 = fmaxf(tm1, __shfl_xor_sync(0xffffffffu, tm1, 1));
            tm1 = fmaxf(tm1, __shfl_xor_sync(0xffffffffu, tm1, 2));

            float nm0 = fmaxf(m0, tm0), nm1 = fmaxf(m1, tm1);
            float co0 = __expf(m0 - nm0), co1 = __expf(m1 - nm1);
            l0 *= co0; l1 *= co1;
#pragma unroll
            for (int nb = 0; nb < 16; nb++) {
                oacc[nb][0] *= co0; oacc[nb][1] *= co0;
                oacc[nb][2] *= co1; oacc[nb][3] *= co1;
            }
            m0 = nm0; m1 = nm1;

            float ls0 = 0.f, ls1 = 0.f;
#pragma unroll
            for (int nb = 0; nb < 8; nb++) {
                c[nb][0] = __expf(c[nb][0] - nm0);
                c[nb][1] = __expf(c[nb][1] - nm0);
                c[nb][2] = __expf(c[nb][2] - nm1);
                c[nb][3] = __expf(c[nb][3] - nm1);
                ls0 += c[nb][0] + c[nb][1];
                ls1 += c[nb][2] + c[nb][3];
            }
            ls0 += __shfl_xor_sync(0xffffffffu, ls0, 1);
            ls0 += __shfl_xor_sync(0xffffffffu, ls0, 2);
            ls1 += __shfl_xor_sync(0xffffffffu, ls1, 1);
            ls1 += __shfl_xor_sync(0xffffffffu, ls1, 2);
            l0 += ls0; l1 += ls1;

#pragma unroll
            for (int kr = 0; kr < 4; kr++) {
                unsigned ap[4];
                ap[0] = h2u(c[2 * kr][0],     c[2 * kr][1]);
                ap[1] = h2u(c[2 * kr][2],     c[2 * kr][3]);
                ap[2] = h2u(c[2 * kr + 1][0], c[2 * kr + 1][1]);
                ap[3] = h2u(c[2 * kr + 1][2], c[2 * kr + 1][3]);
                const uint32_t krowb = vb + (uint32_t)((kr * 16 + vK) * (VSTR * 2));
#pragma unroll
                for (int np = 0; np < 8; np++) {
                    uint32_t a = krowb + (uint32_t)((np * 16 + vC) * 2);
                    unsigned b0, b1, b2, b3;
                    ldmx4t(b0, b1, b2, b3, a);
                    unsigned bv0[2] = {b0, b1};
                    unsigned bv1[2] = {b2, b3};
                    mma_f16(oacc[2 * np], ap, bv0);
                    mma_f16(oacc[2 * np + 1], ap, bv1);
                }
            }
        }
        __syncthreads();
    }

    float inv0 = 1.f / l0, inv1 = 1.f / l1;
    __half* o0 = OH + ((size_t)(b * SS + q0 + row0) * HH + h) * VD;
    __half* o1 = o0 + (size_t)8 * HH * VD;
#pragma unroll
    for (int nb = 0; nb < 16; nb++) {
        *(unsigned*)(o0 + nb * 8 + 2 * tg) = h2u(oacc[nb][0] * inv0, oacc[nb][1] * inv0);
        *(unsigned*)(o1 + nb * 8 + 2 * tg) = h2u(oacc[nb][2] * inv1, oacc[nb][3] * inv1);
    }
}

// ---------------- host launcher ------------------------------------------
extern "C" void kernel_launch(void* const* d_in, const int* in_sizes, int n_in,
                              void* d_out, int out_size)
{
    const float* x         = (const float*)d_in[0];
    const float* w_dq      = (const float*)d_in[1];
    const float* q_a_norm  = (const float*)d_in[2];
    const float* w_uq      = (const float*)d_in[3];
    const float* w_dkv     = (const float*)d_in[4];
    const float* kv_a_norm = (const float*)d_in[5];
    const float* w_ukv     = (const float*)d_in[6];
    const float* w_o       = (const float*)d_in[7];
    float* out = (float*)d_out;

    float *c1, *ct, *st;
    __half *xh, *w1T, *wuqT, *wukvT, *woT, *cqh, *kvah, *oh, *qh, *kvh, *kpeh;
    cudaGetSymbolAddress((void**)&c1,  g_c1);
    cudaGetSymbolAddress((void**)&ct,  g_cos);
    cudaGetSymbolAddress((void**)&st,  g_sin);
    cudaGetSymbolAddress((void**)&xh,    g_xh);
    cudaGetSymbolAddress((void**)&w1T,   g_w1T);
    cudaGetSymbolAddress((void**)&wuqT,  g_wuqT);
    cudaGetSymbolAddress((void**)&wukvT, g_wukvT);
    cudaGetSymbolAddress((void**)&woT,   g_woT);
    cudaGetSymbolAddress((void**)&cqh,   g_cqh);
    cudaGetSymbolAddress((void**)&kvah,  g_kvah);
    cudaGetSymbolAddress((void**)&oh,    g_oh);
    cudaGetSymbolAddress((void**)&qh,    g_qh);
    cudaGetSymbolAddress((void**)&kvh,   g_kvh);
    cudaGetSymbolAddress((void**)&kpeh,  g_kpeh);

    cudaFuncSetAttribute(hgemm_k,  cudaFuncAttributeMaxDynamicSharedMemorySize, HG_SMEM);
    cudaFuncSetAttribute(hgemmh_k, cudaFuncAttributeMaxDynamicSharedMemorySize, HG_SMEM);
    cudaFuncSetAttribute(flash_k,  cudaFuncAttributeMaxDynamicSharedMemorySize, FLASH_SMEM);

    rope_table_k<<<SS, 32>>>(ct, st);

    // convert x; transpose+convert weights (w_dq/w_dkv merged into w1T)
    cvth_k<<<592, 256>>>((const float4*)x, xh, RTOT * DD / 4);
    trth_k<<<dim3(Q_RANK / 32, DD / 32), 256>>>(w_dq, w1T, DD, Q_RANK);
    trth_k<<<dim3((KV_RANK + ROPE_D) / 32, DD / 32), 256>>>(
        w_dkv, w1T + (size_t)Q_RANK * DD, DD, KV_RANK + ROPE_D);
    trth_k<<<dim3((HH * QH) / 32, Q_RANK / 32), 256>>>(w_uq, wuqT, Q_RANK, HH * QH);
    trth_k<<<dim3((HH * KVH) / 32, KV_RANK / 32), 256>>>(w_ukv, wukvT, KV_RANK, HH * KVH);
    trth_k<<<dim3(DD / 32, (HH * VD) / 32), 256>>>(w_o, woT, HH * VD, DD);

    // merged x-projection
    hgemm_k<<<dim3((N1 + 127) / 128, RTOT / 128), 128, HG_SMEM>>>(xh, w1T, c1, RTOT, N1, DD);

    // both norms in one launch
    rmsnorm2_k<<<dim3(RTOT, 2), 256>>>(c1, cqh, kvah, q_a_norm, kv_a_norm);

    // up-projections (fp16 out, feed flash)
    hgemmh_k<<<dim3((HH * QH) / 128, RTOT / 128), 128, HG_SMEM>>>(cqh, wuqT, qh, RTOT, HH * QH, Q_RANK);
    hgemmh_k<<<dim3((HH * KVH) / 128, RTOT / 128), 128, HG_SMEM>>>(kvah, wukvT, kvh, RTOT, HH * KVH, KV_RANK);

    // RoPE: q in-place on half; k_pe from merged fp32 buffer -> half
    rope_qh_k<<<RTOT, dim3(32, HH)>>>(qh, ct, st);
    rope_kh_k<<<RTOT, 32>>>(c1 + Q_RANK + KV_RANK, N1, kpeh, ct, st);

    // attention
    flash_k<<<dim3(SS / FBM, HH, BB), 256, FLASH_SMEM>>>(qh, kvh, kpeh, oh);

    // output projection
    hgemm_k<<<dim3(DD / 128, RTOT / 128), 128, HG_SMEM>>>(oh, woT, out, RTOT, DD, HH * VD);
}